// round 8
// baseline (speedup 1.0000x reference)
#include <cuda_runtime.h>
#include <cuda_bf16.h>
#include <cstdint>

#define H 256
#define W 256
#define CIN 256
#define COMP 64
#define BATCH 4
#define HW (H * W)

__device__ float g_comp[(size_t)BATCH * COMP * HW];     // 64 MiB
__device__ float g_s[(size_t)BATCH * 9 * HW];           // 9 MiB
__device__ __nv_bfloat16 g_wtb[COMP * CIN];             // W bf16 [o][c]

__device__ __forceinline__ float2 ffma2(float2 a, float2 b, float2 c) {
    unsigned long long au = *reinterpret_cast<unsigned long long*>(&a);
    unsigned long long bu = *reinterpret_cast<unsigned long long*>(&b);
    unsigned long long cu = *reinterpret_cast<unsigned long long*>(&c);
    unsigned long long du;
    asm("fma.rn.f32x2 %0, %1, %2, %3;" : "=l"(du) : "l"(au), "l"(bu), "l"(cu));
    return *reinterpret_cast<float2*>(&du);
}

__device__ __forceinline__ void cp_async16z(uint32_t dst, const float* src, int sz) {
    asm volatile("cp.async.ca.shared.global [%0], [%1], 16, %2;"
                 :: "r"(dst), "l"(src), "r"(sz) : "memory");
}
__device__ __forceinline__ void cp_async4z(uint32_t dst, const float* src, int sz) {
    asm volatile("cp.async.ca.shared.global [%0], [%1], 4, %2;"
                 :: "r"(dst), "l"(src), "r"(sz) : "memory");
}
#define CP_COMMIT() asm volatile("cp.async.commit_group;" ::: "memory")
#define CP_WAIT(n)  asm volatile("cp.async.wait_group %0;" :: "n"(n) : "memory")

// ---------------------------------------------------------------------------
// Kernel 0: wc (64x256 fp32, [o][c]) -> g_wtb bf16 same layout
// ---------------------------------------------------------------------------
__global__ void k_wt(const float* __restrict__ wc) {
    int e = blockIdx.x * 256 + threadIdx.x;
    g_wtb[e] = __float2bfloat16(wc[e]);
}

// ---------------------------------------------------------------------------
// Kernel 1: 1x1 compression via mma.sync bf16 m16n8k16.
// CTA: 64 o x 128 p, K=256. 8 warps = 2(o) x 4(p); warp = 32o x 32p.
// x converted fp32->bf16 into smem [c][p] (ldmatrix.trans source);
// W fragments LDG'd from g_wtb (L1-resident).
// ---------------------------------------------------------------------------
__global__ void __launch_bounds__(256, 2) k_compress(const float* __restrict__ x) {
    const int b  = blockIdx.y;
    const int p0 = blockIdx.x * 128;
    const float* xb = x + (size_t)b * CIN * HW;
    float* cb = g_comp + (size_t)b * COMP * HW;

    __shared__ __align__(16) __nv_bfloat16 xs[2][32][136];  // 17408 B

    const int tid  = threadIdx.x;
    const int lane = tid & 31;
    const int warp = tid >> 5;
    const int wo = warp >> 2, wp = warp & 3;
    const int g  = lane >> 2;
    const int c2 = (lane & 3) * 2;

    // staging mapping: 16 floats per thread per chunk
    const int sc = tid >> 3;    // channel row 0..31
    const int sj = tid & 7;     // p-slice 0..7 (16 p each)

    const uint32_t xs_base = (uint32_t)__cvta_generic_to_shared(&xs[0][0][0]);

    float xr[16];
    auto ldx = [&](int chunk) {
        const float* src = xb + (size_t)(chunk * 32 + sc) * HW + p0 + sj * 16;
#pragma unroll
        for (int q = 0; q < 4; q++)
            *(float4*)&xr[q * 4] = *(const float4*)(src + q * 4);
    };
    auto stx = [&](int buf) {
        uint32_t pk[8];
#pragma unroll
        for (int i = 0; i < 8; i++)
            asm("cvt.rn.bf16x2.f32 %0, %1, %2;"
                : "=r"(pk[i]) : "f"(xr[2 * i + 1]), "f"(xr[2 * i]));
        __nv_bfloat16* dst = &xs[buf][sc][sj * 16];
        *(uint4*)dst       = *(uint4*)&pk[0];
        *(uint4*)(dst + 8) = *(uint4*)&pk[4];
    };

    float dacc[2][4][4];
#pragma unroll
    for (int m = 0; m < 2; m++)
#pragma unroll
        for (int n = 0; n < 4; n++)
#pragma unroll
            for (int d = 0; d < 4; d++) dacc[m][n][d] = 0.f;

    ldx(0); stx(0);
    __syncthreads();

    for (int it = 0; it < 8; it++) {
        const int cur = it & 1;
        if (it < 7) ldx(it + 1);            // LDG latency hidden under mma

        // ---- A fragments: direct LDG.32 of bf16 pairs (L1 hits) ----
        const int c0 = it * 32;
        uint32_t a[2][2][4];
#pragma unroll
        for (int m = 0; m < 2; m++) {
            const int ob = wo * 32 + m * 16 + g;
#pragma unroll
            for (int k = 0; k < 2; k++) {
                const int cc = c0 + k * 16 + c2;
                const __nv_bfloat16* wbp = g_wtb + ob * 256 + cc;
                a[m][k][0] = *(const uint32_t*)(wbp);
                a[m][k][1] = *(const uint32_t*)(wbp + 8 * 256);
                a[m][k][2] = *(const uint32_t*)(wbp + 8);
                a[m][k][3] = *(const uint32_t*)(wbp + 8 * 256 + 8);
            }
        }
        // ---- B fragments via ldmatrix.x4.trans ----
        uint32_t bfr[2][2][4];   // [kstep][npair][reg]
#pragma unroll
        for (int k = 0; k < 2; k++)
#pragma unroll
            for (int np = 0; np < 2; np++) {
                uint32_t addr = xs_base + (uint32_t)cur * 8704
                              + (uint32_t)(k * 16 + (lane & 15)) * 272
                              + (uint32_t)(wp * 32 + np * 16 + (lane >> 4) * 8) * 2;
                asm volatile(
                    "ldmatrix.sync.aligned.m8n8.x4.trans.shared.b16 "
                    "{%0,%1,%2,%3}, [%4];"
                    : "=r"(bfr[k][np][0]), "=r"(bfr[k][np][1]),
                      "=r"(bfr[k][np][2]), "=r"(bfr[k][np][3])
                    : "r"(addr));
            }
        // ---- 16 mma ----
#pragma unroll
        for (int m = 0; m < 2; m++)
#pragma unroll
            for (int n = 0; n < 4; n++)
#pragma unroll
                for (int k = 0; k < 2; k++) {
                    uint32_t b0 = bfr[k][n >> 1][(n & 1) * 2];
                    uint32_t b1 = bfr[k][n >> 1][(n & 1) * 2 + 1];
                    asm volatile(
                        "mma.sync.aligned.m16n8k16.row.col.f32.bf16.bf16.f32 "
                        "{%0,%1,%2,%3}, {%4,%5,%6,%7}, {%8,%9}, {%0,%1,%2,%3};"
                        : "+f"(dacc[m][n][0]), "+f"(dacc[m][n][1]),
                          "+f"(dacc[m][n][2]), "+f"(dacc[m][n][3])
                        : "r"(a[m][k][0]), "r"(a[m][k][1]),
                          "r"(a[m][k][2]), "r"(a[m][k][3]),
                          "r"(b0), "r"(b1));
                }

        if (it < 7) stx(cur ^ 1);
        __syncthreads();
    }

    // ---- epilogue: D fragment (row=o, col=p) -> g_comp[o][p] ----
#pragma unroll
    for (int m = 0; m < 2; m++) {
        const int o = wo * 32 + m * 16 + g;
#pragma unroll
        for (int n = 0; n < 4; n++) {
            const int p = p0 + wp * 32 + n * 8 + (lane & 3) * 2;
            *(float2*)(cb + (size_t)o * HW + p) =
                make_float2(dacc[m][n][0], dacc[m][n][1]);
            *(float2*)(cb + (size_t)(o + 8) * HW + p) =
                make_float2(dacc[m][n][2], dacc[m][n][3]);
        }
    }
}

// ---------------------------------------------------------------------------
// Kernel 2: 3x3 conv (64->9) + bias + softmax (unchanged).
// ---------------------------------------------------------------------------
__global__ void __launch_bounds__(256) k_convsoft(const float* __restrict__ wg,
                                                  const float* __restrict__ bg) {
    const int b  = blockIdx.z;
    const int h0 = blockIdx.y * 8;
    const int w0 = blockIdx.x * 64;

    __shared__ float xs[2][8][10][72];
    __shared__ float wsAll[COMP][9][12];

    const int tid = threadIdx.x;
    const int lh  = tid >> 5;
    const int lw  = (tid & 31) * 2;

    const float* compb = g_comp + (size_t)b * COMP * HW;

    const uint32_t xs_base  = (uint32_t)__cvta_generic_to_shared(&xs[0][0][0][0]);
    const uint32_t ws_base  = (uint32_t)__cvta_generic_to_shared(&wsAll[0][0][0]);

#pragma unroll
    for (int i = 0; i < 27; i++) {
        int idx = tid + i * 256;
        if (idx < COMP * 9 * 12) {
            int c = idx / 108;
            int rem = idx - c * 108;
            int tap = rem / 12;
            int q = rem - tap * 12;
            const float* src = (q < 9) ? (wg + (q * COMP + c) * 9 + tap) : wg;
            cp_async4z(ws_base + (uint32_t)idx * 4, src, (q < 9) ? 4 : 0);
        }
    }
    CP_COMMIT();

    int soff[6], goff[6], ssz[6];
    bool is16[6];
#pragma unroll
    for (int s = 0; s < 6; s++) {
        int idx = tid + s * 256;
        is16[s] = false; ssz[s] = -1;
        if (idx < 1440) {
            int c = idx / 180;
            int rem = idx - c * 180;
            int r = rem / 18;
            int k = rem - r * 18;
            int gh = h0 + r - 1;
            bool rowok = (unsigned)gh < 256u;
            int gw, dcol;
            bool colok = true;
            if (k < 16)      { gw = w0 + 4 * k; dcol = 4 + 4 * k; is16[s] = true; }
            else if (k == 16){ gw = w0 - 1;  dcol = 3;  colok = (gw >= 0); }
            else             { gw = w0 + 64; dcol = 68; colok = (gw <= 255); }
            bool ok = rowok && colok;
            if (!ok) { gh = 0; gw = 0; }
            soff[s] = ((c * 10 + r) * 72 + dcol) * 4;
            goff[s] = c * HW + gh * W + gw;
            ssz[s]  = ok ? (is16[s] ? 16 : 4) : 0;
        }
    }

    auto stage = [&](int buf, int c0) {
        const float* base = compb + (size_t)c0 * HW;
        uint32_t dbase = xs_base + (uint32_t)buf * (8 * 10 * 72 * 4);
#pragma unroll
        for (int s = 0; s < 6; s++) {
            if (ssz[s] < 0) continue;
            if (is16[s]) cp_async16z(dbase + soff[s], base + goff[s], ssz[s]);
            else         cp_async4z (dbase + soff[s], base + goff[s], ssz[s]);
        }
        CP_COMMIT();
    };

    float2 acc[2][5];
#pragma unroll
    for (int j = 0; j < 5; j++) {
        float blo = bg[2 * j];
        float bhi = (2 * j + 1 < 9) ? bg[2 * j + 1] : 0.f;
        acc[0][j] = make_float2(blo, bhi);
        acc[1][j] = make_float2(blo, bhi);
    }

    stage(0, 0);

    for (int it = 0; it < 8; it++) {
        const int cur = it & 1;
        if (it + 1 < 8) { stage(cur ^ 1, (it + 1) * 8); CP_WAIT(1); }
        else            { CP_WAIT(0); }
        __syncthreads();
#pragma unroll
        for (int c = 0; c < 8; c++) {
            const int cg = it * 8 + c;
#pragma unroll
            for (int di = 0; di < 3; di++) {
                float2 A = *(const float2*)&xs[cur][c][lh + di][lw + 2];
                float2 B = *(const float2*)&xs[cur][c][lh + di][lw + 4];
                float  C = xs[cur][c][lh + di][lw + 6];
                float2 d[4];
                d[0] = make_float2(A.y, A.y);
                d[1] = make_float2(B.x, B.x);
                d[2] = make_float2(B.y, B.y);
                d[3] = make_float2(C,   C);
#pragma unroll
                for (int tap = 0; tap < 3; tap++) {
                    const float* wrow = &wsAll[cg][di * 3 + tap][0];
                    float4 w0v = *(const float4*)(wrow);
                    float4 w1v = *(const float4*)(wrow + 4);
                    float4 w2v = *(const float4*)(wrow + 8);
                    float2 wq[5];
                    wq[0] = make_float2(w0v.x, w0v.y);
                    wq[1] = make_float2(w0v.z, w0v.w);
                    wq[2] = make_float2(w1v.x, w1v.y);
                    wq[3] = make_float2(w1v.z, w1v.w);
                    wq[4] = make_float2(w2v.x, w2v.y);
#pragma unroll
                    for (int j = 0; j < 5; j++) {
                        acc[0][j] = ffma2(d[tap],     wq[j], acc[0][j]);
                        acc[1][j] = ffma2(d[tap + 1], wq[j], acc[1][j]);
                    }
                }
            }
        }
        __syncthreads();
    }

    float v0[9], v1[9];
#pragma unroll
    for (int j = 0; j < 5; j++) {
        v0[2 * j] = acc[0][j].x;  v1[2 * j] = acc[1][j].x;
        if (2 * j + 1 < 9) { v0[2 * j + 1] = acc[0][j].y; v1[2 * j + 1] = acc[1][j].y; }
    }
    float mA = v0[0], mB = v1[0];
#pragma unroll
    for (int kk = 1; kk < 9; kk++) { mA = fmaxf(mA, v0[kk]); mB = fmaxf(mB, v1[kk]); }
    float sA = 0.f, sB = 0.f;
#pragma unroll
    for (int kk = 0; kk < 9; kk++) {
        v0[kk] = __expf(v0[kk] - mA); sA += v0[kk];
        v1[kk] = __expf(v1[kk] - mB); sB += v1[kk];
    }
    float iA = 1.f / sA, iB = 1.f / sB;
    float* sb = g_s + (size_t)b * 9 * HW;
    const int pbase = (h0 + lh) * W + w0 + lw;
#pragma unroll
    for (int kk = 0; kk < 9; kk++)
        *(float2*)(sb + (size_t)kk * HW + pbase) =
            make_float2(v0[kk] * iA, v1[kk] * iB);
}

// ---------------------------------------------------------------------------
// Kernel 3: direct-gmem 3x3 weighted aggregation, edges via __shfl.
// Thread = 4 px (float4); warp spans the full 128-px row of the block.
// 32 channels per block (grid z = 32).
// ---------------------------------------------------------------------------
__global__ void __launch_bounds__(256) k_aggregate(const float* __restrict__ x,
                                                   float* __restrict__ out) {
    const int bz = blockIdx.z;
    const int b  = bz >> 3;
    const int cg = bz & 7;              // 32-channel group
    const int h0 = blockIdx.y * 8;
    const int w0 = blockIdx.x * 128;

    const int tid  = threadIdx.x;
    const int lane = tid & 31;
    const int lh   = tid >> 5;
    const int w    = w0 + lane * 4;
    const int h    = h0 + lh;

    // per-pixel tap weights for 4 pixels
    const float* sp = g_s + (size_t)b * 9 * HW + (size_t)(h * W + w) * 9;
    const float HAM[9] = {0.0064f, 0.08f, 0.0064f,
                          0.08f,   1.0f,  0.08f,
                          0.0064f, 0.08f, 0.0064f};
    float wv[4][9];
#pragma unroll
    for (int p = 0; p < 4; p++) {
        float s = 0.f;
#pragma unroll
        for (int t = 0; t < 9; t++) { wv[p][t] = HAM[t] * sp[p * 9 + t]; s += wv[p][t]; }
        float inv = 1.f / (s + 1e-8f);
#pragma unroll
        for (int t = 0; t < 9; t++) wv[p][t] *= inv;
    }
    float2 wA[9], wB[9];
#pragma unroll
    for (int t = 0; t < 9; t++) {
        wA[t] = make_float2(wv[0][t], wv[1][t]);
        wB[t] = make_float2(wv[2][t], wv[3][t]);
    }

    const int hm = (h == 0)   ? 1   : h - 1;
    const int hp = (h == 255) ? 254 : h + 1;
    const int rm = hm * W, r0 = h * W, rp = hp * W;
    const bool leftB  = (w0 == 0);
    const bool rightB = (w0 + 128 >= 256);

    const float* xb = x  + ((size_t)b * CIN + cg * 32) * HW;
    float*       ob = out + ((size_t)b * CIN + cg * 32) * HW;

#pragma unroll 2
    for (int c = 0; c < 32; c++) {
        const float* pc = xb + (size_t)c * HW;
        float4 Bm = *(const float4*)(pc + rm + w);
        float4 B0 = *(const float4*)(pc + r0 + w);
        float4 Bp = *(const float4*)(pc + rp + w);

        float Lm = __shfl_up_sync(0xffffffffu, Bm.w, 1);
        float L0 = __shfl_up_sync(0xffffffffu, B0.w, 1);
        float Lp = __shfl_up_sync(0xffffffffu, Bp.w, 1);
        float Rm = __shfl_down_sync(0xffffffffu, Bm.x, 1);
        float R0 = __shfl_down_sync(0xffffffffu, B0.x, 1);
        float Rp = __shfl_down_sync(0xffffffffu, Bp.x, 1);
        if (lane == 0) {
            if (leftB) { Lm = Bm.y; L0 = B0.y; Lp = Bp.y; }
            else       { Lm = pc[rm + w - 1]; L0 = pc[r0 + w - 1]; Lp = pc[rp + w - 1]; }
        }
        if (lane == 31) {
            if (rightB) { Rm = Bm.z; R0 = B0.z; Rp = Bp.z; }
            else        { Rm = pc[rm + w + 4]; R0 = pc[r0 + w + 4]; Rp = pc[rp + w + 4]; }
        }

        float2 aggA = make_float2(0.f, 0.f);
        float2 aggB = make_float2(0.f, 0.f);
        aggA = ffma2(make_float2(Lm,  Bm.x), wA[0], aggA);
        aggA = ffma2(make_float2(Bm.x, Bm.y), wA[1], aggA);
        aggA = ffma2(make_float2(Bm.y, Bm.z), wA[2], aggA);
        aggB = ffma2(make_float2(Bm.y, Bm.z), wB[0], aggB);
        aggB = ffma2(make_float2(Bm.z, Bm.w), wB[1], aggB);
        aggB = ffma2(make_float2(Bm.w, Rm),   wB[2], aggB);

        aggA = ffma2(make_float2(L0,  B0.x), wA[3], aggA);
        aggA = ffma2(make_float2(B0.x, B0.y), wA[4], aggA);
        aggA = ffma2(make_float2(B0.y, B0.z), wA[5], aggA);
        aggB = ffma2(make_float2(B0.y, B0.z), wB[3], aggB);
        aggB = ffma2(make_float2(B0.z, B0.w), wB[4], aggB);
        aggB = ffma2(make_float2(B0.w, R0),   wB[5], aggB);

        aggA = ffma2(make_float2(Lp,  Bp.x), wA[6], aggA);
        aggA = ffma2(make_float2(Bp.x, Bp.y), wA[7], aggA);
        aggA = ffma2(make_float2(Bp.y, Bp.z), wA[8], aggA);
        aggB = ffma2(make_float2(Bp.y, Bp.z), wB[6], aggB);
        aggB = ffma2(make_float2(Bp.z, Bp.w), wB[7], aggB);
        aggB = ffma2(make_float2(Bp.w, Rp),   wB[8], aggB);

        float4 o4;
        o4.x = 2.f * B0.x - aggA.x;
        o4.y = 2.f * B0.y - aggA.y;
        o4.z = 2.f * B0.z - aggB.x;
        o4.w = 2.f * B0.w - aggB.y;
        *(float4*)(ob + (size_t)c * HW + r0 + w) = o4;
    }
}

// ---------------------------------------------------------------------------
extern "C" void kernel_launch(void* const* d_in, const int* in_sizes, int n_in,
                              void* d_out, int out_size) {
    const float* x  = (const float*)d_in[0];
    const float* wc = (const float*)d_in[1];
    const float* wg = (const float*)d_in[2];
    const float* bg = (const float*)d_in[3];
    float* out = (float*)d_out;

    k_wt       <<<64, 256>>>(wc);
    k_compress <<<dim3(HW / 128, BATCH), 256>>>(x);
    k_convsoft <<<dim3(W / 64, H / 8, BATCH), 256>>>(wg, bg);
    k_aggregate<<<dim3(W / 128, H / 8, BATCH * 8), 256>>>(x, out);
}

// round 10
// speedup vs baseline: 2.1809x; 2.1809x over previous
#include <cuda_runtime.h>
#include <cuda_bf16.h>
#include <cstdint>

#define H 256
#define W 256
#define CIN 256
#define COMP 64
#define BATCH 4
#define HW (H * W)

__device__ float g_comp[(size_t)BATCH * COMP * HW];     // 64 MiB
__device__ float g_s[(size_t)BATCH * 9 * HW];           // 9 MiB
__device__ __nv_bfloat16 g_wtb[COMP * CIN];             // W bf16 [o][c]

__device__ __forceinline__ float2 ffma2(float2 a, float2 b, float2 c) {
    unsigned long long au = *reinterpret_cast<unsigned long long*>(&a);
    unsigned long long bu = *reinterpret_cast<unsigned long long*>(&b);
    unsigned long long cu = *reinterpret_cast<unsigned long long*>(&c);
    unsigned long long du;
    asm("fma.rn.f32x2 %0, %1, %2, %3;" : "=l"(du) : "l"(au), "l"(bu), "l"(cu));
    return *reinterpret_cast<float2*>(&du);
}

__device__ __forceinline__ void cp_async16(uint32_t dst, const void* src) {
    asm volatile("cp.async.ca.shared.global [%0], [%1], 16;"
                 :: "r"(dst), "l"(src) : "memory");
}
__device__ __forceinline__ void cp_async16z(uint32_t dst, const float* src, int sz) {
    asm volatile("cp.async.ca.shared.global [%0], [%1], 16, %2;"
                 :: "r"(dst), "l"(src), "r"(sz) : "memory");
}
__device__ __forceinline__ void cp_async4z(uint32_t dst, const float* src, int sz) {
    asm volatile("cp.async.ca.shared.global [%0], [%1], 4, %2;"
                 :: "r"(dst), "l"(src), "r"(sz) : "memory");
}
#define CP_COMMIT() asm volatile("cp.async.commit_group;" ::: "memory")
#define CP_WAIT(n)  asm volatile("cp.async.wait_group %0;" :: "n"(n) : "memory")

// ---------------------------------------------------------------------------
// Kernel 0: wc (64x256 fp32, [o][c]) -> g_wtb bf16 same layout
// ---------------------------------------------------------------------------
__global__ void k_wt(const float* __restrict__ wc) {
    int e = blockIdx.x * 256 + threadIdx.x;
    g_wtb[e] = __float2bfloat16(wc[e]);
}

// ---------------------------------------------------------------------------
// Kernel 1: 1x1 compression via mma.sync bf16 m16n8k16.
// CTA: 64 o x 128 p, K=256. 8 warps = 2(o) x 4(p); warp = 32o x 32p.
// W staged ONCE in smem (528B-pitch rows: 256 data + 8 pad bf16), A via
// ldmatrix.x4; x converted fp32->bf16 into smem [c][p], B via ldmatrix.x4.trans.
// ---------------------------------------------------------------------------
#define WPITCH 264   // bf16 per W row (256 + 8 pad) -> 528 B

__global__ void __launch_bounds__(256, 2) k_compress(const float* __restrict__ x) {
    const int b  = blockIdx.y;
    const int p0 = blockIdx.x * 128;
    const float* xb = x + (size_t)b * CIN * HW;
    float* cb = g_comp + (size_t)b * COMP * HW;

    __shared__ __align__(16) __nv_bfloat16 xs[2][32][136];     // 17408 B
    __shared__ __align__(16) __nv_bfloat16 wsm[COMP][WPITCH];  // 33792 B

    const int tid  = threadIdx.x;
    const int lane = tid & 31;
    const int warp = tid >> 5;
    const int wo = warp >> 2, wp = warp & 3;
    const int g  = lane >> 2;

    const uint32_t xs_base  = (uint32_t)__cvta_generic_to_shared(&xs[0][0][0]);
    const uint32_t wsm_base = (uint32_t)__cvta_generic_to_shared(&wsm[0][0]);

    // ---- stage ALL of W into smem once (2048 cp16, 8/thread) ----
#pragma unroll
    for (int i = 0; i < 8; i++) {
        int idx = tid + i * 256;
        int o  = idx >> 5;        // 0..63
        int ch = idx & 31;        // 0..31 (16B units of 8 bf16)
        cp_async16(wsm_base + (uint32_t)(o * (WPITCH * 2) + ch * 16),
                   g_wtb + o * 256 + ch * 8);
    }
    CP_COMMIT();

    // staging mapping: 16 floats per thread per chunk
    const int sc = tid >> 3;    // channel row 0..31
    const int sj = tid & 7;     // p-slice 0..7 (16 p each)

    float xr[16];
    auto ldx = [&](int chunk) {
        const float* src = xb + (size_t)(chunk * 32 + sc) * HW + p0 + sj * 16;
#pragma unroll
        for (int q = 0; q < 4; q++)
            *(float4*)&xr[q * 4] = *(const float4*)(src + q * 4);
    };
    auto stx = [&](int buf) {
        uint32_t pk[8];
#pragma unroll
        for (int i = 0; i < 8; i++)
            asm("cvt.rn.bf16x2.f32 %0, %1, %2;"
                : "=r"(pk[i]) : "f"(xr[2 * i + 1]), "f"(xr[2 * i]));
        __nv_bfloat16* dst = &xs[buf][sc][sj * 16];
        *(uint4*)dst       = *(uint4*)&pk[0];
        *(uint4*)(dst + 8) = *(uint4*)&pk[4];
    };

    float dacc[2][4][4];
#pragma unroll
    for (int m = 0; m < 2; m++)
#pragma unroll
        for (int n = 0; n < 4; n++)
#pragma unroll
            for (int d = 0; d < 4; d++) dacc[m][n][d] = 0.f;

    ldx(0); stx(0);
    CP_WAIT(0);            // W staged
    __syncthreads();

    // A ldmatrix lane address pieces (row within 16-row tile, 16B col select)
    const int arow = (lane & 7) + ((lane >> 3) & 1) * 8;
    const int acol = (lane >> 4) * 16;

    for (int it = 0; it < 8; it++) {
        const int cur = it & 1;
        if (it < 7) ldx(it + 1);            // LDG latency hidden under mma

        // ---- A fragments via ldmatrix.x4 (non-trans) from wsm ----
        uint32_t a[2][2][4];
#pragma unroll
        for (int m = 0; m < 2; m++)
#pragma unroll
            for (int k = 0; k < 2; k++) {
                uint32_t addr = wsm_base
                              + (uint32_t)(wo * 32 + m * 16 + arow) * (WPITCH * 2)
                              + (uint32_t)(it * 32 + k * 16) * 2 + acol;
                asm volatile(
                    "ldmatrix.sync.aligned.m8n8.x4.shared.b16 "
                    "{%0,%1,%2,%3}, [%4];"
                    : "=r"(a[m][k][0]), "=r"(a[m][k][1]),
                      "=r"(a[m][k][2]), "=r"(a[m][k][3])
                    : "r"(addr));
            }
        // ---- B fragments via ldmatrix.x4.trans ----
        uint32_t bfr[2][2][4];   // [kstep][npair][reg]
#pragma unroll
        for (int k = 0; k < 2; k++)
#pragma unroll
            for (int np = 0; np < 2; np++) {
                uint32_t addr = xs_base + (uint32_t)cur * 8704
                              + (uint32_t)(k * 16 + (lane & 15)) * 272
                              + (uint32_t)(wp * 32 + np * 16 + (lane >> 4) * 8) * 2;
                asm volatile(
                    "ldmatrix.sync.aligned.m8n8.x4.trans.shared.b16 "
                    "{%0,%1,%2,%3}, [%4];"
                    : "=r"(bfr[k][np][0]), "=r"(bfr[k][np][1]),
                      "=r"(bfr[k][np][2]), "=r"(bfr[k][np][3])
                    : "r"(addr));
            }
        // ---- 16 mma ----
#pragma unroll
        for (int m = 0; m < 2; m++)
#pragma unroll
            for (int n = 0; n < 4; n++)
#pragma unroll
                for (int k = 0; k < 2; k++) {
                    uint32_t b0 = bfr[k][n >> 1][(n & 1) * 2];
                    uint32_t b1 = bfr[k][n >> 1][(n & 1) * 2 + 1];
                    asm volatile(
                        "mma.sync.aligned.m16n8k16.row.col.f32.bf16.bf16.f32 "
                        "{%0,%1,%2,%3}, {%4,%5,%6,%7}, {%8,%9}, {%0,%1,%2,%3};"
                        : "+f"(dacc[m][n][0]), "+f"(dacc[m][n][1]),
                          "+f"(dacc[m][n][2]), "+f"(dacc[m][n][3])
                        : "r"(a[m][k][0]), "r"(a[m][k][1]),
                          "r"(a[m][k][2]), "r"(a[m][k][3]),
                          "r"(b0), "r"(b1));
                }

        if (it < 7) stx(cur ^ 1);
        __syncthreads();
    }

    // ---- epilogue: D fragment (row=o, col=p) -> g_comp[o][p] ----
#pragma unroll
    for (int m = 0; m < 2; m++) {
        const int o = wo * 32 + m * 16 + g;
#pragma unroll
        for (int n = 0; n < 4; n++) {
            const int p = p0 + wp * 32 + n * 8 + (lane & 3) * 2;
            *(float2*)(cb + (size_t)o * HW + p) =
                make_float2(dacc[m][n][0], dacc[m][n][1]);
            *(float2*)(cb + (size_t)(o + 8) * HW + p) =
                make_float2(dacc[m][n][2], dacc[m][n][3]);
        }
    }
}

// ---------------------------------------------------------------------------
// Kernel 2: 3x3 conv (64->9) + bias + softmax (unchanged).
// ---------------------------------------------------------------------------
__global__ void __launch_bounds__(256) k_convsoft(const float* __restrict__ wg,
                                                  const float* __restrict__ bg) {
    const int b  = blockIdx.z;
    const int h0 = blockIdx.y * 8;
    const int w0 = blockIdx.x * 64;

    __shared__ float xs[2][8][10][72];
    __shared__ float wsAll[COMP][9][12];

    const int tid = threadIdx.x;
    const int lh  = tid >> 5;
    const int lw  = (tid & 31) * 2;

    const float* compb = g_comp + (size_t)b * COMP * HW;

    const uint32_t xs_base  = (uint32_t)__cvta_generic_to_shared(&xs[0][0][0][0]);
    const uint32_t ws_base  = (uint32_t)__cvta_generic_to_shared(&wsAll[0][0][0]);

#pragma unroll
    for (int i = 0; i < 27; i++) {
        int idx = tid + i * 256;
        if (idx < COMP * 9 * 12) {
            int c = idx / 108;
            int rem = idx - c * 108;
            int tap = rem / 12;
            int q = rem - tap * 12;
            const float* src = (q < 9) ? (wg + (q * COMP + c) * 9 + tap) : wg;
            cp_async4z(ws_base + (uint32_t)idx * 4, src, (q < 9) ? 4 : 0);
        }
    }
    CP_COMMIT();

    int soff[6], goff[6], ssz[6];
    bool is16[6];
#pragma unroll
    for (int s = 0; s < 6; s++) {
        int idx = tid + s * 256;
        is16[s] = false; ssz[s] = -1;
        if (idx < 1440) {
            int c = idx / 180;
            int rem = idx - c * 180;
            int r = rem / 18;
            int k = rem - r * 18;
            int gh = h0 + r - 1;
            bool rowok = (unsigned)gh < 256u;
            int gw, dcol;
            bool colok = true;
            if (k < 16)      { gw = w0 + 4 * k; dcol = 4 + 4 * k; is16[s] = true; }
            else if (k == 16){ gw = w0 - 1;  dcol = 3;  colok = (gw >= 0); }
            else             { gw = w0 + 64; dcol = 68; colok = (gw <= 255); }
            bool ok = rowok && colok;
            if (!ok) { gh = 0; gw = 0; }
            soff[s] = ((c * 10 + r) * 72 + dcol) * 4;
            goff[s] = c * HW + gh * W + gw;
            ssz[s]  = ok ? (is16[s] ? 16 : 4) : 0;
        }
    }

    auto stage = [&](int buf, int c0) {
        const float* base = compb + (size_t)c0 * HW;
        uint32_t dbase = xs_base + (uint32_t)buf * (8 * 10 * 72 * 4);
#pragma unroll
        for (int s = 0; s < 6; s++) {
            if (ssz[s] < 0) continue;
            if (is16[s]) cp_async16z(dbase + soff[s], base + goff[s], ssz[s]);
            else         cp_async4z (dbase + soff[s], base + goff[s], ssz[s]);
        }
        CP_COMMIT();
    };

    float2 acc[2][5];
#pragma unroll
    for (int j = 0; j < 5; j++) {
        float blo = bg[2 * j];
        float bhi = (2 * j + 1 < 9) ? bg[2 * j + 1] : 0.f;
        acc[0][j] = make_float2(blo, bhi);
        acc[1][j] = make_float2(blo, bhi);
    }

    stage(0, 0);

    for (int it = 0; it < 8; it++) {
        const int cur = it & 1;
        if (it + 1 < 8) { stage(cur ^ 1, (it + 1) * 8); CP_WAIT(1); }
        else            { CP_WAIT(0); }
        __syncthreads();
#pragma unroll
        for (int c = 0; c < 8; c++) {
            const int cg = it * 8 + c;
#pragma unroll
            for (int di = 0; di < 3; di++) {
                float2 A = *(const float2*)&xs[cur][c][lh + di][lw + 2];
                float2 B = *(const float2*)&xs[cur][c][lh + di][lw + 4];
                float  C = xs[cur][c][lh + di][lw + 6];
                float2 d[4];
                d[0] = make_float2(A.y, A.y);
                d[1] = make_float2(B.x, B.x);
                d[2] = make_float2(B.y, B.y);
                d[3] = make_float2(C,   C);
#pragma unroll
                for (int tap = 0; tap < 3; tap++) {
                    const float* wrow = &wsAll[cg][di * 3 + tap][0];
                    float4 w0v = *(const float4*)(wrow);
                    float4 w1v = *(const float4*)(wrow + 4);
                    float4 w2v = *(const float4*)(wrow + 8);
                    float2 wq[5];
                    wq[0] = make_float2(w0v.x, w0v.y);
                    wq[1] = make_float2(w0v.z, w0v.w);
                    wq[2] = make_float2(w1v.x, w1v.y);
                    wq[3] = make_float2(w1v.z, w1v.w);
                    wq[4] = make_float2(w2v.x, w2v.y);
#pragma unroll
                    for (int j = 0; j < 5; j++) {
                        acc[0][j] = ffma2(d[tap],     wq[j], acc[0][j]);
                        acc[1][j] = ffma2(d[tap + 1], wq[j], acc[1][j]);
                    }
                }
            }
        }
        __syncthreads();
    }

    float v0[9], v1[9];
#pragma unroll
    for (int j = 0; j < 5; j++) {
        v0[2 * j] = acc[0][j].x;  v1[2 * j] = acc[1][j].x;
        if (2 * j + 1 < 9) { v0[2 * j + 1] = acc[0][j].y; v1[2 * j + 1] = acc[1][j].y; }
    }
    float mA = v0[0], mB = v1[0];
#pragma unroll
    for (int kk = 1; kk < 9; kk++) { mA = fmaxf(mA, v0[kk]); mB = fmaxf(mB, v1[kk]); }
    float sA = 0.f, sB = 0.f;
#pragma unroll
    for (int kk = 0; kk < 9; kk++) {
        v0[kk] = __expf(v0[kk] - mA); sA += v0[kk];
        v1[kk] = __expf(v1[kk] - mB); sB += v1[kk];
    }
    float iA = 1.f / sA, iB = 1.f / sB;
    float* sb = g_s + (size_t)b * 9 * HW;
    const int pbase = (h0 + lh) * W + w0 + lw;
#pragma unroll
    for (int kk = 0; kk < 9; kk++)
        *(float2*)(sb + (size_t)kk * HW + pbase) =
            make_float2(v0[kk] * iA, v1[kk] * iB);
}

// ---------------------------------------------------------------------------
// Kernel 3: direct-gmem 3x3 weighted aggregation (R7 version).
// Thread = 4 consecutive px (float4) at one h; no smem, no barriers.
// ---------------------------------------------------------------------------
__global__ void __launch_bounds__(256, 2) k_aggregate(const float* __restrict__ x,
                                                      float* __restrict__ out) {
    const int bz = blockIdx.z;
    const int b  = bz >> 2;
    const int cg = bz & 3;
    const int h0 = blockIdx.y * 8;
    const int w0 = blockIdx.x * 128;

    const int tid = threadIdx.x;
    const int lh  = tid >> 5;
    const int w   = w0 + (tid & 31) * 4;
    const int h   = h0 + lh;

    const float* sp = g_s + (size_t)b * 9 * HW + (size_t)(h * W + w) * 9;
    const float HAM[9] = {0.0064f, 0.08f, 0.0064f,
                          0.08f,   1.0f,  0.08f,
                          0.0064f, 0.08f, 0.0064f};
    float wv[4][9];
#pragma unroll
    for (int p = 0; p < 4; p++) {
        float s = 0.f;
#pragma unroll
        for (int t = 0; t < 9; t++) { wv[p][t] = HAM[t] * sp[p * 9 + t]; s += wv[p][t]; }
        float inv = 1.f / (s + 1e-8f);
#pragma unroll
        for (int t = 0; t < 9; t++) wv[p][t] *= inv;
    }
    float2 wA[9], wB[9];
#pragma unroll
    for (int t = 0; t < 9; t++) {
        wA[t] = make_float2(wv[0][t], wv[1][t]);
        wB[t] = make_float2(wv[2][t], wv[3][t]);
    }

    const int hm = (h == 0)   ? 1   : h - 1;
    const int hp = (h == 255) ? 254 : h + 1;
    const int wl = (w == 0)   ? 1   : w - 1;
    const int wr = (w + 4 > 255) ? 254 : w + 4;
    const int rm = hm * W, r0 = h * W, rp = hp * W;

    const float* xb = x  + ((size_t)b * CIN + cg * 64) * HW;
    float*       ob = out + ((size_t)b * CIN + cg * 64) * HW;

#pragma unroll 2
    for (int c = 0; c < 64; c++) {
        const float* pc = xb + (size_t)c * HW;
        float4 Bm = *(const float4*)(pc + rm + w);
        float  Lm = pc[rm + wl], Rm = pc[rm + wr];
        float4 B0 = *(const float4*)(pc + r0 + w);
        float  L0 = pc[r0 + wl], R0 = pc[r0 + wr];
        float4 Bp = *(const float4*)(pc + rp + w);
        float  Lp = pc[rp + wl], Rp = pc[rp + wr];

        float2 aggA = make_float2(0.f, 0.f);
        float2 aggB = make_float2(0.f, 0.f);
        aggA = ffma2(make_float2(Lm,  Bm.x), wA[0], aggA);
        aggA = ffma2(make_float2(Bm.x, Bm.y), wA[1], aggA);
        aggA = ffma2(make_float2(Bm.y, Bm.z), wA[2], aggA);
        aggB = ffma2(make_float2(Bm.y, Bm.z), wB[0], aggB);
        aggB = ffma2(make_float2(Bm.z, Bm.w), wB[1], aggB);
        aggB = ffma2(make_float2(Bm.w, Rm),   wB[2], aggB);

        aggA = ffma2(make_float2(L0,  B0.x), wA[3], aggA);
        aggA = ffma2(make_float2(B0.x, B0.y), wA[4], aggA);
        aggA = ffma2(make_float2(B0.y, B0.z), wA[5], aggA);
        aggB = ffma2(make_float2(B0.y, B0.z), wB[3], aggB);
        aggB = ffma2(make_float2(B0.z, B0.w), wB[4], aggB);
        aggB = ffma2(make_float2(B0.w, R0),   wB[5], aggB);

        aggA = ffma2(make_float2(Lp,  Bp.x), wA[6], aggA);
        aggA = ffma2(make_float2(Bp.x, Bp.y), wA[7], aggA);
        aggA = ffma2(make_float2(Bp.y, Bp.z), wA[8], aggA);
        aggB = ffma2(make_float2(Bp.y, Bp.z), wB[6], aggB);
        aggB = ffma2(make_float2(Bp.z, Bp.w), wB[7], aggB);
        aggB = ffma2(make_float2(Bp.w, Rp),   wB[8], aggB);

        float4 o4;
        o4.x = 2.f * B0.x - aggA.x;
        o4.y = 2.f * B0.y - aggA.y;
        o4.z = 2.f * B0.z - aggB.x;
        o4.w = 2.f * B0.w - aggB.y;
        *(float4*)(ob + (size_t)c * HW + r0 + w) = o4;
    }
}

// ---------------------------------------------------------------------------
extern "C" void kernel_launch(void* const* d_in, const int* in_sizes, int n_in,
                              void* d_out, int out_size) {
    const float* x  = (const float*)d_in[0];
    const float* wc = (const float*)d_in[1];
    const float* wg = (const float*)d_in[2];
    const float* bg = (const float*)d_in[3];
    float* out = (float*)d_out;

    k_wt       <<<64, 256>>>(wc);
    k_compress <<<dim3(HW / 128, BATCH), 256>>>(x);
    k_convsoft <<<dim3(W / 64, H / 8, BATCH), 256>>>(wg, bg);
    k_aggregate<<<dim3(W / 128, H / 8, BATCH * 4), 256>>>(x, out);
}

// round 11
// speedup vs baseline: 2.2630x; 1.0376x over previous
#include <cuda_runtime.h>
#include <cuda_bf16.h>
#include <cstdint>

#define H 256
#define W 256
#define CIN 256
#define COMP 64
#define BATCH 4
#define HW (H * W)

__device__ float g_comp[(size_t)BATCH * COMP * HW];     // 64 MiB
__device__ float g_s[(size_t)BATCH * 9 * HW];           // 9 MiB
__device__ __nv_bfloat16 g_wtb[COMP * CIN];             // W bf16 [o][c]

__device__ __forceinline__ float2 ffma2(float2 a, float2 b, float2 c) {
    unsigned long long au = *reinterpret_cast<unsigned long long*>(&a);
    unsigned long long bu = *reinterpret_cast<unsigned long long*>(&b);
    unsigned long long cu = *reinterpret_cast<unsigned long long*>(&c);
    unsigned long long du;
    asm("fma.rn.f32x2 %0, %1, %2, %3;" : "=l"(du) : "l"(au), "l"(bu), "l"(cu));
    return *reinterpret_cast<float2*>(&du);
}

__device__ __forceinline__ void cp_async16(uint32_t dst, const void* src) {
    asm volatile("cp.async.ca.shared.global [%0], [%1], 16;"
                 :: "r"(dst), "l"(src) : "memory");
}
#define CP_COMMIT() asm volatile("cp.async.commit_group;" ::: "memory")
#define CP_WAIT(n)  asm volatile("cp.async.wait_group %0;" :: "n"(n) : "memory")

// ---------------------------------------------------------------------------
// Kernel 0: wc (64x256 fp32, [o][c]) -> g_wtb bf16 same layout
// ---------------------------------------------------------------------------
__global__ void k_wt(const float* __restrict__ wc) {
    int e = blockIdx.x * 256 + threadIdx.x;
    g_wtb[e] = __float2bfloat16(wc[e]);
}

// ---------------------------------------------------------------------------
// Kernel 1: 1x1 compression via mma.sync bf16 m16n8k16 (unchanged from R10).
// ---------------------------------------------------------------------------
#define WPITCH 264   // bf16 per W row (256 + 8 pad) -> 528 B

__global__ void __launch_bounds__(256, 2) k_compress(const float* __restrict__ x) {
    const int b  = blockIdx.y;
    const int p0 = blockIdx.x * 128;
    const float* xb = x + (size_t)b * CIN * HW;
    float* cb = g_comp + (size_t)b * COMP * HW;

    __shared__ __align__(16) __nv_bfloat16 xs[2][32][136];     // 17408 B
    __shared__ __align__(16) __nv_bfloat16 wsm[COMP][WPITCH];  // 33792 B

    const int tid  = threadIdx.x;
    const int lane = tid & 31;
    const int warp = tid >> 5;
    const int wo = warp >> 2, wp = warp & 3;
    const int g  = lane >> 2;

    const uint32_t xs_base  = (uint32_t)__cvta_generic_to_shared(&xs[0][0][0]);
    const uint32_t wsm_base = (uint32_t)__cvta_generic_to_shared(&wsm[0][0]);

#pragma unroll
    for (int i = 0; i < 8; i++) {
        int idx = tid + i * 256;
        int o  = idx >> 5;
        int ch = idx & 31;
        cp_async16(wsm_base + (uint32_t)(o * (WPITCH * 2) + ch * 16),
                   g_wtb + o * 256 + ch * 8);
    }
    CP_COMMIT();

    const int sc = tid >> 3;
    const int sj = tid & 7;

    float xr[16];
    auto ldx = [&](int chunk) {
        const float* src = xb + (size_t)(chunk * 32 + sc) * HW + p0 + sj * 16;
#pragma unroll
        for (int q = 0; q < 4; q++)
            *(float4*)&xr[q * 4] = *(const float4*)(src + q * 4);
    };
    auto stx = [&](int buf) {
        uint32_t pk[8];
#pragma unroll
        for (int i = 0; i < 8; i++)
            asm("cvt.rn.bf16x2.f32 %0, %1, %2;"
                : "=r"(pk[i]) : "f"(xr[2 * i + 1]), "f"(xr[2 * i]));
        __nv_bfloat16* dst = &xs[buf][sc][sj * 16];
        *(uint4*)dst       = *(uint4*)&pk[0];
        *(uint4*)(dst + 8) = *(uint4*)&pk[4];
    };

    float dacc[2][4][4];
#pragma unroll
    for (int m = 0; m < 2; m++)
#pragma unroll
        for (int n = 0; n < 4; n++)
#pragma unroll
            for (int d = 0; d < 4; d++) dacc[m][n][d] = 0.f;

    ldx(0); stx(0);
    CP_WAIT(0);
    __syncthreads();

    const int arow = (lane & 7) + ((lane >> 3) & 1) * 8;
    const int acol = (lane >> 4) * 16;

    for (int it = 0; it < 8; it++) {
        const int cur = it & 1;
        if (it < 7) ldx(it + 1);

        uint32_t a[2][2][4];
#pragma unroll
        for (int m = 0; m < 2; m++)
#pragma unroll
            for (int k = 0; k < 2; k++) {
                uint32_t addr = wsm_base
                              + (uint32_t)(wo * 32 + m * 16 + arow) * (WPITCH * 2)
                              + (uint32_t)(it * 32 + k * 16) * 2 + acol;
                asm volatile(
                    "ldmatrix.sync.aligned.m8n8.x4.shared.b16 "
                    "{%0,%1,%2,%3}, [%4];"
                    : "=r"(a[m][k][0]), "=r"(a[m][k][1]),
                      "=r"(a[m][k][2]), "=r"(a[m][k][3])
                    : "r"(addr));
            }
        uint32_t bfr[2][2][4];
#pragma unroll
        for (int k = 0; k < 2; k++)
#pragma unroll
            for (int np = 0; np < 2; np++) {
                uint32_t addr = xs_base + (uint32_t)cur * 8704
                              + (uint32_t)(k * 16 + (lane & 15)) * 272
                              + (uint32_t)(wp * 32 + np * 16 + (lane >> 4) * 8) * 2;
                asm volatile(
                    "ldmatrix.sync.aligned.m8n8.x4.trans.shared.b16 "
                    "{%0,%1,%2,%3}, [%4];"
                    : "=r"(bfr[k][np][0]), "=r"(bfr[k][np][1]),
                      "=r"(bfr[k][np][2]), "=r"(bfr[k][np][3])
                    : "r"(addr));
            }
#pragma unroll
        for (int m = 0; m < 2; m++)
#pragma unroll
            for (int n = 0; n < 4; n++)
#pragma unroll
                for (int k = 0; k < 2; k++) {
                    uint32_t b0 = bfr[k][n >> 1][(n & 1) * 2];
                    uint32_t b1 = bfr[k][n >> 1][(n & 1) * 2 + 1];
                    asm volatile(
                        "mma.sync.aligned.m16n8k16.row.col.f32.bf16.bf16.f32 "
                        "{%0,%1,%2,%3}, {%4,%5,%6,%7}, {%8,%9}, {%0,%1,%2,%3};"
                        : "+f"(dacc[m][n][0]), "+f"(dacc[m][n][1]),
                          "+f"(dacc[m][n][2]), "+f"(dacc[m][n][3])
                        : "r"(a[m][k][0]), "r"(a[m][k][1]),
                          "r"(a[m][k][2]), "r"(a[m][k][3]),
                          "r"(b0), "r"(b1));
                }

        if (it < 7) stx(cur ^ 1);
        __syncthreads();
    }

#pragma unroll
    for (int m = 0; m < 2; m++) {
        const int o = wo * 32 + m * 16 + g;
#pragma unroll
        for (int n = 0; n < 4; n++) {
            const int p = p0 + wp * 32 + n * 8 + (lane & 3) * 2;
            *(float2*)(cb + (size_t)o * HW + p) =
                make_float2(dacc[m][n][0], dacc[m][n][1]);
            *(float2*)(cb + (size_t)(o + 8) * HW + p) =
                make_float2(dacc[m][n][2], dacc[m][n][3]);
        }
    }
}

// ---------------------------------------------------------------------------
// Kernel 2 v2: 3x3 conv (64->9) + bias + softmax via mma.sync bf16.
// Tile 8h x 64w, 8 warps (warp = one h row). 9 tap-GEMMs, K = 64c in 4 ksteps.
// B: 3 w-shifted bf16 copies of comp halo tile in smem (aligned ldmatrix).
// A: w_gen repacked [tap][kk16][c64] bf16 (kk rows 9-15 zero).
// Softmax over kk done on D fragments with shfl.bfly reductions.
// ---------------------------------------------------------------------------
__global__ void __launch_bounds__(256, 2) k_convsoft(const float* __restrict__ wg,
                                                     const float* __restrict__ bg) {
    const int b  = blockIdx.z;
    const int h0 = blockIdx.y * 8;
    const int w0 = blockIdx.x * 64;

    // wsA: [tap][kk 16 rows][72 bf16 pitch] -> 144B pitch (odd 16B units)
    __shared__ __align__(16) __nv_bfloat16 wsA[9][16][72];   // 20736 B
    // xsb: [c 16][flat 1928 bf16]; per c: [r 10][s 3][p 64] + 8 pad
    __shared__ __align__(16) __nv_bfloat16 xsb[16][1928];    // 61696 B

    const int tid  = threadIdx.x;
    const int lane = tid & 31;
    const int lh   = tid >> 5;                 // warp = output row

    const float* compb = g_comp + (size_t)b * COMP * HW;

    // ---- stage wsA: zero, then fill kk<9 ----
    {
        uint32_t* wz = (uint32_t*)&wsA[0][0][0];
        for (int i = tid; i < 9 * 16 * 72 / 2; i += 256) wz[i] = 0u;
    }
    __syncthreads();
    for (int i = tid; i < 9 * 9 * 64; i += 256) {
        int tap = i / 576;
        int rem = i - tap * 576;
        int kk = rem >> 6;
        int c  = rem & 63;
        wsA[tap][kk][c] = __float2bfloat16(wg[(kk * COMP + c) * 9 + tap]);
    }

    const uint32_t xsb_base = (uint32_t)__cvta_generic_to_shared(&xsb[0][0]);
    const uint32_t wsA_base = (uint32_t)__cvta_generic_to_shared(&wsA[0][0][0]);

    // ---- conversion tasks: thread t<160 -> (c, r) ----
    const int cc = tid / 10;
    const int rr = tid - cc * 10;
    const bool cvt_act = (tid < 160);
    const int gh = h0 + rr - 1;
    const bool rowok = ((unsigned)gh < 256u);

    float4 P4[18];
    auto cvload = [&](int kstep) {
        if (!cvt_act) return;
        const float* src = compb + (size_t)(kstep * 16 + cc) * HW + gh * W + (w0 - 4);
        if (rowok && w0 > 0) P4[0] = *(const float4*)src;
        else P4[0] = make_float4(0.f, 0.f, 0.f, 0.f);
#pragma unroll
        for (int q = 1; q < 17; q++)
            P4[q] = rowok ? *(const float4*)(src + 4 * q)
                          : make_float4(0.f, 0.f, 0.f, 0.f);
        if (rowok && w0 < 192) P4[17] = *(const float4*)(src + 68);
        else P4[17] = make_float4(0.f, 0.f, 0.f, 0.f);
    };
    auto cvstore = [&]() {
        if (!cvt_act) return;
        uint32_t P[36];
#pragma unroll
        for (int q = 0; q < 18; q++) {
            asm("cvt.rn.bf16x2.f32 %0, %1, %2;" : "=r"(P[2*q])   : "f"(P4[q].y), "f"(P4[q].x));
            asm("cvt.rn.bf16x2.f32 %0, %1, %2;" : "=r"(P[2*q+1]) : "f"(P4[q].w), "f"(P4[q].z));
        }
        uint32_t O[34];
#pragma unroll
        for (int j = 1; j < 34; j++)
            asm("prmt.b32 %0, %1, %2, 0x5432;" : "=r"(O[j]) : "r"(P[j]), "r"(P[j + 1]));
        uint32_t dbase = xsb_base + (uint32_t)(cc * 3856 + rr * 384);
#pragma unroll
        for (int t = 0; t < 8; t++) {
            asm volatile("st.shared.v4.b32 [%0], {%1,%2,%3,%4};" ::
              "r"(dbase + t * 16),
              "r"(O[1+4*t]), "r"(O[2+4*t]), "r"(O[3+4*t]), "r"(O[4+4*t]));
            asm volatile("st.shared.v4.b32 [%0], {%1,%2,%3,%4};" ::
              "r"(dbase + 128 + t * 16),
              "r"(P[2+4*t]), "r"(P[3+4*t]), "r"(P[4+4*t]), "r"(P[5+4*t]));
            asm volatile("st.shared.v4.b32 [%0], {%1,%2,%3,%4};" ::
              "r"(dbase + 256 + t * 16),
              "r"(O[2+4*t]), "r"(O[3+4*t]), "r"(O[4+4*t]), "r"(O[5+4*t]));
        }
    };

    float dacc[8][4];
#pragma unroll
    for (int i = 0; i < 8; i++)
#pragma unroll
        for (int d = 0; d < 4; d++) dacc[i][d] = 0.f;

    cvload(0);
    cvstore();
    __syncthreads();     // wsA + chunk 0 ready

    const int arow = (lane & 7) + ((lane >> 3) & 1) * 8;
    const int acol = (lane >> 4) * 16;
    const uint32_t bcol = (uint32_t)((lane >> 4) * 8) * 2;

    for (int kstep = 0; kstep < 4; kstep++) {
        if (kstep < 3) cvload(kstep + 1);

#pragma unroll
        for (int tap = 0; tap < 9; tap++) {
            const int di = tap / 3;
            const int dj = tap - di * 3;
            uint32_t a0, a1, a2, a3;
            {
                uint32_t aaddr = wsA_base + (uint32_t)(tap * 2304 + arow * 144
                               + kstep * 32) + acol;
                asm volatile(
                    "ldmatrix.sync.aligned.m8n8.x4.shared.b16 "
                    "{%0,%1,%2,%3}, [%4];"
                    : "=r"(a0), "=r"(a1), "=r"(a2), "=r"(a3) : "r"(aaddr));
            }
            const uint32_t brow = xsb_base + (uint32_t)((lane & 15) * 3856
                                + (lh + di) * 384 + dj * 128) + bcol;
#pragma unroll
            for (int np = 0; np < 4; np++) {
                uint32_t b0, b1, b2, b3;
                asm volatile(
                    "ldmatrix.sync.aligned.m8n8.x4.trans.shared.b16 "
                    "{%0,%1,%2,%3}, [%4];"
                    : "=r"(b0), "=r"(b1), "=r"(b2), "=r"(b3)
                    : "r"(brow + (uint32_t)(np * 32)));
                asm volatile(
                    "mma.sync.aligned.m16n8k16.row.col.f32.bf16.bf16.f32 "
                    "{%0,%1,%2,%3}, {%4,%5,%6,%7}, {%8,%9}, {%0,%1,%2,%3};"
                    : "+f"(dacc[2*np][0]), "+f"(dacc[2*np][1]),
                      "+f"(dacc[2*np][2]), "+f"(dacc[2*np][3])
                    : "r"(a0), "r"(a1), "r"(a2), "r"(a3), "r"(b0), "r"(b1));
                asm volatile(
                    "mma.sync.aligned.m16n8k16.row.col.f32.bf16.bf16.f32 "
                    "{%0,%1,%2,%3}, {%4,%5,%6,%7}, {%8,%9}, {%0,%1,%2,%3};"
                    : "+f"(dacc[2*np+1][0]), "+f"(dacc[2*np+1][1]),
                      "+f"(dacc[2*np+1][2]), "+f"(dacc[2*np+1][3])
                    : "r"(a0), "r"(a1), "r"(a2), "r"(a3), "r"(b2), "r"(b3));
            }
        }
        __syncthreads();          // all warps done reading xsb
        if (kstep < 3) cvstore(); // overwrite in place
        __syncthreads();
    }

    // ---- softmax over kk (rows) per pixel (col), store to g_s ----
    const int row_lo = lane >> 2;           // 0..7
    const bool hi = (row_lo == 0);          // this lane also holds row 8
    const float bias_lo = bg[row_lo];
    const float bias8 = bg[8];
    float* sb = g_s + (size_t)b * 9 * HW;
    const int pxbase = (h0 + lh) * W + w0 + 2 * (lane & 3);

#pragma unroll
    for (int i = 0; i < 8; i++) {
        float d0 = dacc[i][0] + bias_lo;
        float d1 = dacc[i][1] + bias_lo;
        float d2 = hi ? dacc[i][2] + bias8 : -1e30f;
        float d3 = hi ? dacc[i][3] + bias8 : -1e30f;

        float m0 = fmaxf(d0, d2);
        float m1 = fmaxf(d1, d3);
#pragma unroll
        for (int mk = 4; mk <= 16; mk <<= 1) {
            m0 = fmaxf(m0, __shfl_xor_sync(0xffffffffu, m0, mk));
            m1 = fmaxf(m1, __shfl_xor_sync(0xffffffffu, m1, mk));
        }
        float e0 = __expf(d0 - m0);
        float e1 = __expf(d1 - m1);
        float e2 = hi ? __expf(d2 - m0) : 0.f;
        float e3 = hi ? __expf(d3 - m1) : 0.f;
        float s0 = e0 + e2, s1 = e1 + e3;
#pragma unroll
        for (int mk = 4; mk <= 16; mk <<= 1) {
            s0 += __shfl_xor_sync(0xffffffffu, s0, mk);
            s1 += __shfl_xor_sync(0xffffffffu, s1, mk);
        }
        float i0 = 1.f / s0, i1 = 1.f / s1;
        const int px = pxbase + i * 8;
        *(float2*)(sb + (size_t)row_lo * HW + px) = make_float2(e0 * i0, e1 * i1);
        if (hi)
            *(float2*)(sb + (size_t)8 * HW + px) = make_float2(e2 * i0, e3 * i1);
    }
}

// ---------------------------------------------------------------------------
// Kernel 3: direct-gmem 3x3 weighted aggregation (unchanged from R10).
// ---------------------------------------------------------------------------
__global__ void __launch_bounds__(256, 2) k_aggregate(const float* __restrict__ x,
                                                      float* __restrict__ out) {
    const int bz = blockIdx.z;
    const int b  = bz >> 2;
    const int cg = bz & 3;
    const int h0 = blockIdx.y * 8;
    const int w0 = blockIdx.x * 128;

    const int tid = threadIdx.x;
    const int lh  = tid >> 5;
    const int w   = w0 + (tid & 31) * 4;
    const int h   = h0 + lh;

    const float* sp = g_s + (size_t)b * 9 * HW + (size_t)(h * W + w) * 9;
    const float HAM[9] = {0.0064f, 0.08f, 0.0064f,
                          0.08f,   1.0f,  0.08f,
                          0.0064f, 0.08f, 0.0064f};
    float wv[4][9];
#pragma unroll
    for (int p = 0; p < 4; p++) {
        float s = 0.f;
#pragma unroll
        for (int t = 0; t < 9; t++) { wv[p][t] = HAM[t] * sp[p * 9 + t]; s += wv[p][t]; }
        float inv = 1.f / (s + 1e-8f);
#pragma unroll
        for (int t = 0; t < 9; t++) wv[p][t] *= inv;
    }
    float2 wA[9], wB[9];
#pragma unroll
    for (int t = 0; t < 9; t++) {
        wA[t] = make_float2(wv[0][t], wv[1][t]);
        wB[t] = make_float2(wv[2][t], wv[3][t]);
    }

    const int hm = (h == 0)   ? 1   : h - 1;
    const int hp = (h == 255) ? 254 : h + 1;
    const int wl = (w == 0)   ? 1   : w - 1;
    const int wr = (w + 4 > 255) ? 254 : w + 4;
    const int rm = hm * W, r0 = h * W, rp = hp * W;

    const float* xb = x  + ((size_t)b * CIN + cg * 64) * HW;
    float*       ob = out + ((size_t)b * CIN + cg * 64) * HW;

#pragma unroll 2
    for (int c = 0; c < 64; c++) {
        const float* pc = xb + (size_t)c * HW;
        float4 Bm = *(const float4*)(pc + rm + w);
        float  Lm = pc[rm + wl], Rm = pc[rm + wr];
        float4 B0 = *(const float4*)(pc + r0 + w);
        float  L0 = pc[r0 + wl], R0 = pc[r0 + wr];
        float4 Bp = *(const float4*)(pc + rp + w);
        float  Lp = pc[rp + wl], Rp = pc[rp + wr];

        float2 aggA = make_float2(0.f, 0.f);
        float2 aggB = make_float2(0.f, 0.f);
        aggA = ffma2(make_float2(Lm,  Bm.x), wA[0], aggA);
        aggA = ffma2(make_float2(Bm.x, Bm.y), wA[1], aggA);
        aggA = ffma2(make_float2(Bm.y, Bm.z), wA[2], aggA);
        aggB = ffma2(make_float2(Bm.y, Bm.z), wB[0], aggB);
        aggB = ffma2(make_float2(Bm.z, Bm.w), wB[1], aggB);
        aggB = ffma2(make_float2(Bm.w, Rm),   wB[2], aggB);

        aggA = ffma2(make_float2(L0,  B0.x), wA[3], aggA);
        aggA = ffma2(make_float2(B0.x, B0.y), wA[4], aggA);
        aggA = ffma2(make_float2(B0.y, B0.z), wA[5], aggA);
        aggB = ffma2(make_float2(B0.y, B0.z), wB[3], aggB);
        aggB = ffma2(make_float2(B0.z, B0.w), wB[4], aggB);
        aggB = ffma2(make_float2(B0.w, R0),   wB[5], aggB);

        aggA = ffma2(make_float2(Lp,  Bp.x), wA[6], aggA);
        aggA = ffma2(make_float2(Bp.x, Bp.y), wA[7], aggA);
        aggA = ffma2(make_float2(Bp.y, Bp.z), wA[8], aggA);
        aggB = ffma2(make_float2(Bp.y, Bp.z), wB[6], aggB);
        aggB = ffma2(make_float2(Bp.z, Bp.w), wB[7], aggB);
        aggB = ffma2(make_float2(Bp.w, Rp),   wB[8], aggB);

        float4 o4;
        o4.x = 2.f * B0.x - aggA.x;
        o4.y = 2.f * B0.y - aggA.y;
        o4.z = 2.f * B0.z - aggB.x;
        o4.w = 2.f * B0.w - aggB.y;
        *(float4*)(ob + (size_t)c * HW + r0 + w) = o4;
    }
}

// ---------------------------------------------------------------------------
extern "C" void kernel_launch(void* const* d_in, const int* in_sizes, int n_in,
                              void* d_out, int out_size) {
    const float* x  = (const float*)d_in[0];
    const float* wc = (const float*)d_in[1];
    const float* wg = (const float*)d_in[2];
    const float* bg = (const float*)d_in[3];
    float* out = (float*)d_out;

    k_wt       <<<64, 256>>>(wc);
    k_compress <<<dim3(HW / 128, BATCH), 256>>>(x);
    k_convsoft <<<dim3(W / 64, H / 8, BATCH), 256>>>(wg, bg);
    k_aggregate<<<dim3(W / 128, H / 8, BATCH * 4), 256>>>(x, out);
}

// round 12
// speedup vs baseline: 2.3230x; 1.0265x over previous
#include <cuda_runtime.h>
#include <cuda_bf16.h>
#include <cstdint>

#define H 256
#define W 256
#define CIN 256
#define COMP 64
#define BATCH 4
#define HW (H * W)

__device__ float g_comp[(size_t)BATCH * COMP * HW];     // 64 MiB
__device__ float g_s[(size_t)BATCH * 9 * HW];           // 9 MiB
__device__ __nv_bfloat16 g_wtb[COMP * CIN];             // W bf16 [o][c]

__device__ __forceinline__ float2 ffma2(float2 a, float2 b, float2 c) {
    unsigned long long au = *reinterpret_cast<unsigned long long*>(&a);
    unsigned long long bu = *reinterpret_cast<unsigned long long*>(&b);
    unsigned long long cu = *reinterpret_cast<unsigned long long*>(&c);
    unsigned long long du;
    asm("fma.rn.f32x2 %0, %1, %2, %3;" : "=l"(du) : "l"(au), "l"(bu), "l"(cu));
    return *reinterpret_cast<float2*>(&du);
}

__device__ __forceinline__ void cp_async16(uint32_t dst, const void* src) {
    asm volatile("cp.async.ca.shared.global [%0], [%1], 16;"
                 :: "r"(dst), "l"(src) : "memory");
}
#define CP_COMMIT() asm volatile("cp.async.commit_group;" ::: "memory")
#define CP_WAIT(n)  asm volatile("cp.async.wait_group %0;" :: "n"(n) : "memory")

// ---------------------------------------------------------------------------
// Kernel 0: wc (64x256 fp32, [o][c]) -> g_wtb bf16 same layout
// ---------------------------------------------------------------------------
__global__ void k_wt(const float* __restrict__ wc) {
    int e = blockIdx.x * 256 + threadIdx.x;
    g_wtb[e] = __float2bfloat16(wc[e]);
}

// ---------------------------------------------------------------------------
// Kernel 1: 1x1 compression via mma.sync bf16 m16n8k16 (unchanged from R10).
// ---------------------------------------------------------------------------
#define WPITCH 264   // bf16 per W row (256 + 8 pad) -> 528 B

__global__ void __launch_bounds__(256, 2) k_compress(const float* __restrict__ x) {
    const int b  = blockIdx.y;
    const int p0 = blockIdx.x * 128;
    const float* xb = x + (size_t)b * CIN * HW;
    float* cb = g_comp + (size_t)b * COMP * HW;

    __shared__ __align__(16) __nv_bfloat16 xs[2][32][136];     // 17408 B
    __shared__ __align__(16) __nv_bfloat16 wsm[COMP][WPITCH];  // 33792 B

    const int tid  = threadIdx.x;
    const int lane = tid & 31;
    const int warp = tid >> 5;
    const int wo = warp >> 2, wp = warp & 3;
    const int g  = lane >> 2;

    const uint32_t xs_base  = (uint32_t)__cvta_generic_to_shared(&xs[0][0][0]);
    const uint32_t wsm_base = (uint32_t)__cvta_generic_to_shared(&wsm[0][0]);

#pragma unroll
    for (int i = 0; i < 8; i++) {
        int idx = tid + i * 256;
        int o  = idx >> 5;
        int ch = idx & 31;
        cp_async16(wsm_base + (uint32_t)(o * (WPITCH * 2) + ch * 16),
                   g_wtb + o * 256 + ch * 8);
    }
    CP_COMMIT();

    const int sc = tid >> 3;
    const int sj = tid & 7;

    float xr[16];
    auto ldx = [&](int chunk) {
        const float* src = xb + (size_t)(chunk * 32 + sc) * HW + p0 + sj * 16;
#pragma unroll
        for (int q = 0; q < 4; q++)
            *(float4*)&xr[q * 4] = *(const float4*)(src + q * 4);
    };
    auto stx = [&](int buf) {
        uint32_t pk[8];
#pragma unroll
        for (int i = 0; i < 8; i++)
            asm("cvt.rn.bf16x2.f32 %0, %1, %2;"
                : "=r"(pk[i]) : "f"(xr[2 * i + 1]), "f"(xr[2 * i]));
        __nv_bfloat16* dst = &xs[buf][sc][sj * 16];
        *(uint4*)dst       = *(uint4*)&pk[0];
        *(uint4*)(dst + 8) = *(uint4*)&pk[4];
    };

    float dacc[2][4][4];
#pragma unroll
    for (int m = 0; m < 2; m++)
#pragma unroll
        for (int n = 0; n < 4; n++)
#pragma unroll
            for (int d = 0; d < 4; d++) dacc[m][n][d] = 0.f;

    ldx(0); stx(0);
    CP_WAIT(0);
    __syncthreads();

    const int arow = (lane & 7) + ((lane >> 3) & 1) * 8;
    const int acol = (lane >> 4) * 16;

    for (int it = 0; it < 8; it++) {
        const int cur = it & 1;
        if (it < 7) ldx(it + 1);

        uint32_t a[2][2][4];
#pragma unroll
        for (int m = 0; m < 2; m++)
#pragma unroll
            for (int k = 0; k < 2; k++) {
                uint32_t addr = wsm_base
                              + (uint32_t)(wo * 32 + m * 16 + arow) * (WPITCH * 2)
                              + (uint32_t)(it * 32 + k * 16) * 2 + acol;
                asm volatile(
                    "ldmatrix.sync.aligned.m8n8.x4.shared.b16 "
                    "{%0,%1,%2,%3}, [%4];"
                    : "=r"(a[m][k][0]), "=r"(a[m][k][1]),
                      "=r"(a[m][k][2]), "=r"(a[m][k][3])
                    : "r"(addr));
            }
        uint32_t bfr[2][2][4];
#pragma unroll
        for (int k = 0; k < 2; k++)
#pragma unroll
            for (int np = 0; np < 2; np++) {
                uint32_t addr = xs_base + (uint32_t)cur * 8704
                              + (uint32_t)(k * 16 + (lane & 15)) * 272
                              + (uint32_t)(wp * 32 + np * 16 + (lane >> 4) * 8) * 2;
                asm volatile(
                    "ldmatrix.sync.aligned.m8n8.x4.trans.shared.b16 "
                    "{%0,%1,%2,%3}, [%4];"
                    : "=r"(bfr[k][np][0]), "=r"(bfr[k][np][1]),
                      "=r"(bfr[k][np][2]), "=r"(bfr[k][np][3])
                    : "r"(addr));
            }
#pragma unroll
        for (int m = 0; m < 2; m++)
#pragma unroll
            for (int n = 0; n < 4; n++)
#pragma unroll
                for (int k = 0; k < 2; k++) {
                    uint32_t b0 = bfr[k][n >> 1][(n & 1) * 2];
                    uint32_t b1 = bfr[k][n >> 1][(n & 1) * 2 + 1];
                    asm volatile(
                        "mma.sync.aligned.m16n8k16.row.col.f32.bf16.bf16.f32 "
                        "{%0,%1,%2,%3}, {%4,%5,%6,%7}, {%8,%9}, {%0,%1,%2,%3};"
                        : "+f"(dacc[m][n][0]), "+f"(dacc[m][n][1]),
                          "+f"(dacc[m][n][2]), "+f"(dacc[m][n][3])
                        : "r"(a[m][k][0]), "r"(a[m][k][1]),
                          "r"(a[m][k][2]), "r"(a[m][k][3]),
                          "r"(b0), "r"(b1));
                }

        if (it < 7) stx(cur ^ 1);
        __syncthreads();
    }

#pragma unroll
    for (int m = 0; m < 2; m++) {
        const int o = wo * 32 + m * 16 + g;
#pragma unroll
        for (int n = 0; n < 4; n++) {
            const int p = p0 + wp * 32 + n * 8 + (lane & 3) * 2;
            *(float2*)(cb + (size_t)o * HW + p) =
                make_float2(dacc[m][n][0], dacc[m][n][1]);
            *(float2*)(cb + (size_t)(o + 8) * HW + p) =
                make_float2(dacc[m][n][2], dacc[m][n][3]);
        }
    }
}

// ---------------------------------------------------------------------------
// Kernel 2 v2: 3x3 conv (64->9) + bias + softmax via mma.sync bf16
// (unchanged from R11).
// ---------------------------------------------------------------------------
__global__ void __launch_bounds__(256, 2) k_convsoft(const float* __restrict__ wg,
                                                     const float* __restrict__ bg) {
    const int b  = blockIdx.z;
    const int h0 = blockIdx.y * 8;
    const int w0 = blockIdx.x * 64;

    __shared__ __align__(16) __nv_bfloat16 wsA[9][16][72];   // 20736 B
    __shared__ __align__(16) __nv_bfloat16 xsb[16][1928];    // 61696 B

    const int tid  = threadIdx.x;
    const int lane = tid & 31;
    const int lh   = tid >> 5;

    const float* compb = g_comp + (size_t)b * COMP * HW;

    {
        uint32_t* wz = (uint32_t*)&wsA[0][0][0];
        for (int i = tid; i < 9 * 16 * 72 / 2; i += 256) wz[i] = 0u;
    }
    __syncthreads();
    for (int i = tid; i < 9 * 9 * 64; i += 256) {
        int tap = i / 576;
        int rem = i - tap * 576;
        int kk = rem >> 6;
        int c  = rem & 63;
        wsA[tap][kk][c] = __float2bfloat16(wg[(kk * COMP + c) * 9 + tap]);
    }

    const uint32_t xsb_base = (uint32_t)__cvta_generic_to_shared(&xsb[0][0]);
    const uint32_t wsA_base = (uint32_t)__cvta_generic_to_shared(&wsA[0][0][0]);

    const int cc = tid / 10;
    const int rr = tid - cc * 10;
    const bool cvt_act = (tid < 160);
    const int gh = h0 + rr - 1;
    const bool rowok = ((unsigned)gh < 256u);

    float4 P4[18];
    auto cvload = [&](int kstep) {
        if (!cvt_act) return;
        const float* src = compb + (size_t)(kstep * 16 + cc) * HW + gh * W + (w0 - 4);
        if (rowok && w0 > 0) P4[0] = *(const float4*)src;
        else P4[0] = make_float4(0.f, 0.f, 0.f, 0.f);
#pragma unroll
        for (int q = 1; q < 17; q++)
            P4[q] = rowok ? *(const float4*)(src + 4 * q)
                          : make_float4(0.f, 0.f, 0.f, 0.f);
        if (rowok && w0 < 192) P4[17] = *(const float4*)(src + 68);
        else P4[17] = make_float4(0.f, 0.f, 0.f, 0.f);
    };
    auto cvstore = [&]() {
        if (!cvt_act) return;
        uint32_t P[36];
#pragma unroll
        for (int q = 0; q < 18; q++) {
            asm("cvt.rn.bf16x2.f32 %0, %1, %2;" : "=r"(P[2*q])   : "f"(P4[q].y), "f"(P4[q].x));
            asm("cvt.rn.bf16x2.f32 %0, %1, %2;" : "=r"(P[2*q+1]) : "f"(P4[q].w), "f"(P4[q].z));
        }
        uint32_t O[34];
#pragma unroll
        for (int j = 1; j < 34; j++)
            asm("prmt.b32 %0, %1, %2, 0x5432;" : "=r"(O[j]) : "r"(P[j]), "r"(P[j + 1]));
        uint32_t dbase = xsb_base + (uint32_t)(cc * 3856 + rr * 384);
#pragma unroll
        for (int t = 0; t < 8; t++) {
            asm volatile("st.shared.v4.b32 [%0], {%1,%2,%3,%4};" ::
              "r"(dbase + t * 16),
              "r"(O[1+4*t]), "r"(O[2+4*t]), "r"(O[3+4*t]), "r"(O[4+4*t]));
            asm volatile("st.shared.v4.b32 [%0], {%1,%2,%3,%4};" ::
              "r"(dbase + 128 + t * 16),
              "r"(P[2+4*t]), "r"(P[3+4*t]), "r"(P[4+4*t]), "r"(P[5+4*t]));
            asm volatile("st.shared.v4.b32 [%0], {%1,%2,%3,%4};" ::
              "r"(dbase + 256 + t * 16),
              "r"(O[2+4*t]), "r"(O[3+4*t]), "r"(O[4+4*t]), "r"(O[5+4*t]));
        }
    };

    float dacc[8][4];
#pragma unroll
    for (int i = 0; i < 8; i++)
#pragma unroll
        for (int d = 0; d < 4; d++) dacc[i][d] = 0.f;

    cvload(0);
    cvstore();
    __syncthreads();

    const int arow = (lane & 7) + ((lane >> 3) & 1) * 8;
    const int acol = (lane >> 4) * 16;
    const uint32_t bcol = (uint32_t)((lane >> 4) * 8) * 2;

    for (int kstep = 0; kstep < 4; kstep++) {
        if (kstep < 3) cvload(kstep + 1);

#pragma unroll
        for (int tap = 0; tap < 9; tap++) {
            const int di = tap / 3;
            const int dj = tap - di * 3;
            uint32_t a0, a1, a2, a3;
            {
                uint32_t aaddr = wsA_base + (uint32_t)(tap * 2304 + arow * 144
                               + kstep * 32) + acol;
                asm volatile(
                    "ldmatrix.sync.aligned.m8n8.x4.shared.b16 "
                    "{%0,%1,%2,%3}, [%4];"
                    : "=r"(a0), "=r"(a1), "=r"(a2), "=r"(a3) : "r"(aaddr));
            }
            const uint32_t brow = xsb_base + (uint32_t)((lane & 15) * 3856
                                + (lh + di) * 384 + dj * 128) + bcol;
#pragma unroll
            for (int np = 0; np < 4; np++) {
                uint32_t b0, b1, b2, b3;
                asm volatile(
                    "ldmatrix.sync.aligned.m8n8.x4.trans.shared.b16 "
                    "{%0,%1,%2,%3}, [%4];"
                    : "=r"(b0), "=r"(b1), "=r"(b2), "=r"(b3)
                    : "r"(brow + (uint32_t)(np * 32)));
                asm volatile(
                    "mma.sync.aligned.m16n8k16.row.col.f32.bf16.bf16.f32 "
                    "{%0,%1,%2,%3}, {%4,%5,%6,%7}, {%8,%9}, {%0,%1,%2,%3};"
                    : "+f"(dacc[2*np][0]), "+f"(dacc[2*np][1]),
                      "+f"(dacc[2*np][2]), "+f"(dacc[2*np][3])
                    : "r"(a0), "r"(a1), "r"(a2), "r"(a3), "r"(b0), "r"(b1));
                asm volatile(
                    "mma.sync.aligned.m16n8k16.row.col.f32.bf16.bf16.f32 "
                    "{%0,%1,%2,%3}, {%4,%5,%6,%7}, {%8,%9}, {%0,%1,%2,%3};"
                    : "+f"(dacc[2*np+1][0]), "+f"(dacc[2*np+1][1]),
                      "+f"(dacc[2*np+1][2]), "+f"(dacc[2*np+1][3])
                    : "r"(a0), "r"(a1), "r"(a2), "r"(a3), "r"(b2), "r"(b3));
            }
        }
        __syncthreads();
        if (kstep < 3) cvstore();
        __syncthreads();
    }

    const int row_lo = lane >> 2;
    const bool hi = (row_lo == 0);
    const float bias_lo = bg[row_lo];
    const float bias8 = bg[8];
    float* sb = g_s + (size_t)b * 9 * HW;
    const int pxbase = (h0 + lh) * W + w0 + 2 * (lane & 3);

#pragma unroll
    for (int i = 0; i < 8; i++) {
        float d0 = dacc[i][0] + bias_lo;
        float d1 = dacc[i][1] + bias_lo;
        float d2 = hi ? dacc[i][2] + bias8 : -1e30f;
        float d3 = hi ? dacc[i][3] + bias8 : -1e30f;

        float m0 = fmaxf(d0, d2);
        float m1 = fmaxf(d1, d3);
#pragma unroll
        for (int mk = 4; mk <= 16; mk <<= 1) {
            m0 = fmaxf(m0, __shfl_xor_sync(0xffffffffu, m0, mk));
            m1 = fmaxf(m1, __shfl_xor_sync(0xffffffffu, m1, mk));
        }
        float e0 = __expf(d0 - m0);
        float e1 = __expf(d1 - m1);
        float e2 = hi ? __expf(d2 - m0) : 0.f;
        float e3 = hi ? __expf(d3 - m1) : 0.f;
        float s0 = e0 + e2, s1 = e1 + e3;
#pragma unroll
        for (int mk = 4; mk <= 16; mk <<= 1) {
            s0 += __shfl_xor_sync(0xffffffffu, s0, mk);
            s1 += __shfl_xor_sync(0xffffffffu, s1, mk);
        }
        float i0 = 1.f / s0, i1 = 1.f / s1;
        const int px = pxbase + i * 8;
        *(float2*)(sb + (size_t)row_lo * HW + px) = make_float2(e0 * i0, e1 * i1);
        if (hi)
            *(float2*)(sb + (size_t)8 * HW + px) = make_float2(e2 * i0, e3 * i1);
    }
}

// ---------------------------------------------------------------------------
// Kernel 3 v2: direct-gmem 3x3 weighted aggregation, 2 px x 2 rows per thread.
// Block tile 64w x 16h; rows reused in registers (3x -> 2x row redundancy),
// 8B lane stride -> 2 L1 wavefronts per load.
// ---------------------------------------------------------------------------
__global__ void __launch_bounds__(256, 2) k_aggregate(const float* __restrict__ x,
                                                      float* __restrict__ out) {
    const int bz = blockIdx.z;
    const int b  = bz >> 2;
    const int cg = bz & 3;
    const int h0 = blockIdx.y * 16;
    const int w0 = blockIdx.x * 64;

    const int tid  = threadIdx.x;
    const int lane = tid & 31;
    const int lh   = tid >> 5;
    const int w    = w0 + lane * 2;
    const int h    = h0 + 2 * lh;          // even; thread does rows h, h+1

    // ---- per-pixel tap weights for 2 rows x 2 px ----
    const float HAM[9] = {0.0064f, 0.08f, 0.0064f,
                          0.08f,   1.0f,  0.08f,
                          0.0064f, 0.08f, 0.0064f};
    float2 wR0[9], wR1[9];
    {
        const float* sp0 = g_s + (size_t)b * 9 * HW + (size_t)(h * W + w) * 9;
        const float* sp1 = sp0 + (size_t)W * 9;
        float a0[9], a1[9], b0[9], b1[9];
        float sa0 = 0.f, sa1 = 0.f, sb0 = 0.f, sb1 = 0.f;
#pragma unroll
        for (int t = 0; t < 9; t++) {
            a0[t] = HAM[t] * sp0[t];      sa0 += a0[t];
            a1[t] = HAM[t] * sp0[9 + t];  sa1 += a1[t];
            b0[t] = HAM[t] * sp1[t];      sb0 += b0[t];
            b1[t] = HAM[t] * sp1[9 + t];  sb1 += b1[t];
        }
        float ia0 = 1.f / (sa0 + 1e-8f), ia1 = 1.f / (sa1 + 1e-8f);
        float ib0 = 1.f / (sb0 + 1e-8f), ib1 = 1.f / (sb1 + 1e-8f);
#pragma unroll
        for (int t = 0; t < 9; t++) {
            wR0[t] = make_float2(a0[t] * ia0, a1[t] * ia1);
            wR1[t] = make_float2(b0[t] * ib0, b1[t] * ib1);
        }
    }

    // reflect-padded row/col offsets (constant over channel loop)
    const int ra = (h == 0) ? 1 : h - 1;           // row h-1
    const int rd = (h + 1 == 255) ? 254 : h + 2;   // row h+2
    const int wl = (w == 0)   ? 1   : w - 1;
    const int wr = (w == 254) ? 254 : w + 2;
    const int oa = ra * W, ob2 = h * W, oc = (h + 1) * W, od = rd * W;

    const float* xb = x  + ((size_t)b * CIN + cg * 64) * HW;
    float*       ob = out + ((size_t)b * CIN + cg * 64) * HW;

#pragma unroll 2
    for (int c = 0; c < 64; c++) {
        const float* pc = xb + (size_t)c * HW;
        float2 A2 = *(const float2*)(pc + oa + w);
        float  Al = pc[oa + wl], Ar = pc[oa + wr];
        float2 B2 = *(const float2*)(pc + ob2 + w);
        float  Bl = pc[ob2 + wl], Br = pc[ob2 + wr];
        float2 C2 = *(const float2*)(pc + oc + w);
        float  Cl = pc[oc + wl], Cr = pc[oc + wr];
        float2 D2 = *(const float2*)(pc + od + w);
        float  Dl = pc[od + wl], Dr = pc[od + wr];

        // output row h: rows A,B,C with wR0
        float2 g0 = make_float2(0.f, 0.f);
        g0 = ffma2(make_float2(Al,  A2.x), wR0[0], g0);
        g0 = ffma2(A2,                     wR0[1], g0);
        g0 = ffma2(make_float2(A2.y, Ar),  wR0[2], g0);
        g0 = ffma2(make_float2(Bl,  B2.x), wR0[3], g0);
        g0 = ffma2(B2,                     wR0[4], g0);
        g0 = ffma2(make_float2(B2.y, Br),  wR0[5], g0);
        g0 = ffma2(make_float2(Cl,  C2.x), wR0[6], g0);
        g0 = ffma2(C2,                     wR0[7], g0);
        g0 = ffma2(make_float2(C2.y, Cr),  wR0[8], g0);

        // output row h+1: rows B,C,D with wR1
        float2 g1 = make_float2(0.f, 0.f);
        g1 = ffma2(make_float2(Bl,  B2.x), wR1[0], g1);
        g1 = ffma2(B2,                     wR1[1], g1);
        g1 = ffma2(make_float2(B2.y, Br),  wR1[2], g1);
        g1 = ffma2(make_float2(Cl,  C2.x), wR1[3], g1);
        g1 = ffma2(C2,                     wR1[4], g1);
        g1 = ffma2(make_float2(C2.y, Cr),  wR1[5], g1);
        g1 = ffma2(make_float2(Dl,  D2.x), wR1[6], g1);
        g1 = ffma2(D2,                     wR1[7], g1);
        g1 = ffma2(make_float2(D2.y, Dr),  wR1[8], g1);

        float* po = ob + (size_t)c * HW;
        *(float2*)(po + ob2 + w) = make_float2(2.f * B2.x - g0.x,
                                               2.f * B2.y - g0.y);
        *(float2*)(po + oc + w)  = make_float2(2.f * C2.x - g1.x,
                                               2.f * C2.y - g1.y);
    }
}

// ---------------------------------------------------------------------------
extern "C" void kernel_launch(void* const* d_in, const int* in_sizes, int n_in,
                              void* d_out, int out_size) {
    const float* x  = (const float*)d_in[0];
    const float* wc = (const float*)d_in[1];
    const float* wg = (const float*)d_in[2];
    const float* bg = (const float*)d_in[3];
    float* out = (float*)d_out;

    k_wt       <<<64, 256>>>(wc);
    k_compress <<<dim3(HW / 128, BATCH), 256>>>(x);
    k_convsoft <<<dim3(W / 64, H / 8, BATCH), 256>>>(wg, bg);
    k_aggregate<<<dim3(W / 64, H / 16, BATCH * 4), 256>>>(x, out);
}